// round 14
// baseline (speedup 1.0000x reference)
#include <cuda_runtime.h>
#include <cuda_fp16.h>
#include <cstdint>

// Problem constants
#define TT 8
#define HH 64
#define WW 64
#define CC 256
#define HEADS 8
#define WS 7
#define NNB 147
#define NPIX (TT*HH*WW)                 // 32768
#define ATTN_ELEMS (HEADS*TT*HH*WW*NNB) // 38,535,168
#define PER_HEAD_FLOW (TT*HH*WW*NNB*3)  // 14,450,688
#define NW 512                          // W rows (2*CC)

// Scratch
__device__ __half g_qh[(size_t)NPIX * CC];   // q fp16 [pix][256]
__device__ __half g_kh[(size_t)NPIX * CC];   // k fp16 [pix][256]
__device__ __half g_xh[(size_t)NPIX * CC];   // x hi
__device__ __half g_wh[(size_t)NW * CC];     // W hi
__device__ __half g_wl[(size_t)NW * CC];     // W lo

// ---------------- common helpers ----------------
__device__ __forceinline__ int reflect_idx(int idx) {
    int m = idx % 126;
    if (m < 0) m += 126;
    return (m > 63) ? (126 - m) : m;
}

__device__ __forceinline__ uint32_t h2_bits(__half2 v) {
    return *reinterpret_cast<uint32_t*>(&v);
}

__device__ __forceinline__ uint32_t smem_u32(const void* p) {
    uint32_t a;
    asm("{ .reg .u64 t; cvta.to.shared.u64 t, %1; cvt.u32.u64 %0, t; }" : "=r"(a) : "l"(p));
    return a;
}

__device__ __forceinline__ void cp16(uint32_t dst, const void* src) {
    asm volatile("cp.async.ca.shared.global [%0], [%1], 16;" :: "r"(dst), "l"(src));
}
#define CP_COMMIT() asm volatile("cp.async.commit_group;" ::: "memory")
#define CP_WAIT(n)  asm volatile("cp.async.wait_group %0;" :: "n"(n) : "memory")

#define LDSM4(r, a) \
    asm volatile("ldmatrix.sync.aligned.m8n8.x4.shared.b16 {%0,%1,%2,%3}, [%4];" \
                 : "=r"((r)[0]), "=r"((r)[1]), "=r"((r)[2]), "=r"((r)[3]) : "r"(a))

#define MMA16816(d, a, b0, b1) \
    asm volatile("mma.sync.aligned.m16n8k16.row.col.f32.f16.f16.f32 " \
                 "{%0,%1,%2,%3}, {%4,%5,%6,%7}, {%8,%9}, {%0,%1,%2,%3};" \
                 : "+f"((d)[0]), "+f"((d)[1]), "+f"((d)[2]), "+f"((d)[3]) \
                 : "r"((a)[0]), "r"((a)[1]), "r"((a)[2]), "r"((a)[3]), "r"(b0), "r"(b1))

// ---------------- Kernel 0: fp32 -> fp16 split ----------------
// x: hi only (2-term GEMM). W: hi + lo.
#define NV4X ((NPIX*CC)/4)   // 2,097,152
#define NV4W ((NW*CC)/4)     // 32,768

__global__ __launch_bounds__(256)
void convert_split(const float* __restrict__ x, const float* __restrict__ Wm) {
    const int total = NV4X + NV4W;
    for (int i = blockIdx.x * blockDim.x + threadIdx.x; i < total; i += gridDim.x * blockDim.x) {
        const float4 v = (i < NV4X) ? ((const float4*)x)[i] : ((const float4*)Wm)[i - NV4X];
        __half2 h01 = __floats2half2_rn(v.x, v.y);
        __half2 h23 = __floats2half2_rn(v.z, v.w);
        uint2 hv = make_uint2(h2_bits(h01), h2_bits(h23));
        if (i < NV4X) {
            ((uint2*)g_xh)[i] = hv;
        } else {
            float2 r01 = __half22float2(h01);
            float2 r23 = __half22float2(h23);
            __half2 l01 = __floats2half2_rn(v.x - r01.x, v.y - r01.y);
            __half2 l23 = __floats2half2_rn(v.z - r23.x, v.w - r23.y);
            ((uint2*)g_wh)[i - NV4X] = hv;
            ((uint2*)g_wl)[i - NV4X] = make_uint2(h2_bits(l01), h2_bits(l23));
        }
    }
}

// ---------------- Kernel 1: HMMA 2-term GEMM ----------------
// q|k[m][n] = sum_k x[m][k]*W[n][k] approx= xh*(wh+wl); fp32 accum HMMA
#define BM 128
#define BN 128
#define BK 32
#define NIT (CC/BK)                 // 8
#define PADH 40                     // halves per smem row (80B)
#define TILE_HALVES (128*PADH)
#define STAGE_HALVES (3*TILE_HALVES)
#define GSMEM (2*STAGE_HALVES*2)    // 61440 bytes

__device__ __forceinline__ void issue_stage(int it, int stage, int m0, int n0,
                                            uint32_t sbase, int tid) {
    const int kc = it * BK;
    const int r_lo = tid >> 2;
    const int c = (tid & 3) << 3;
#pragma unroll
    for (int q = 0; q < 6; q++) {
        const int tile = q >> 1;          // 0:xh 1:wh 2:wl
        const int r = ((q & 1) << 6) + r_lo;
        const __half* src;
        if (tile == 0)      src = g_xh + (size_t)(m0 + r) * CC + kc + c;
        else if (tile == 1) src = g_wh + (size_t)(n0 + r) * CC + kc + c;
        else                src = g_wl + (size_t)(n0 + r) * CC + kc + c;
        const uint32_t dst = sbase +
            (uint32_t)((stage * STAGE_HALVES + tile * TILE_HALVES + r * PADH + c) * 2);
        cp16(dst, src);
    }
}

__global__ __launch_bounds__(256)
void gemm_hmma(void) {
    extern __shared__ __half smem[];
    const uint32_t sbase = smem_u32(smem);
    const int tid = threadIdx.x;
    const int wid = tid >> 5;
    const int lane = tid & 31;

    const int n0 = blockIdx.x * BN;
    const int m0 = blockIdx.y * BM;
    const bool is_k = (n0 >= CC);

    const int wm = (wid >> 1) * 32;
    const int wn = (wid & 1) * 64;
    const int l15 = lane & 15;
    const int kofs = (lane >> 4) << 3;

    float acc[2][8][4];
#pragma unroll
    for (int i = 0; i < 2; i++)
#pragma unroll
        for (int j = 0; j < 8; j++)
#pragma unroll
            for (int c = 0; c < 4; c++) acc[i][j][c] = 0.0f;

    issue_stage(0, 0, m0, n0, sbase, tid);
    CP_COMMIT();

    for (int it = 0; it < NIT; it++) {
        if (it + 1 < NIT) {
            issue_stage(it + 1, (it + 1) & 1, m0, n0, sbase, tid);
            CP_COMMIT();
            CP_WAIT(1);
        } else {
            CP_WAIT(0);
        }
        __syncthreads();

        const uint32_t st = sbase + (uint32_t)(((it & 1) * STAGE_HALVES) * 2);
        const uint32_t ah_b = st;
        const uint32_t bh_b = st + TILE_HALVES * 2;
        const uint32_t bl_b = st + 2 * TILE_HALVES * 2;

#pragma unroll
        for (int kk = 0; kk < BK; kk += 16) {
            uint32_t ah[2][4];
#pragma unroll
            for (int mt = 0; mt < 2; mt++) {
                const uint32_t off = (uint32_t)(((wm + mt * 16 + l15) * PADH + kk + kofs) * 2);
                LDSM4(ah[mt], ah_b + off);
            }
#pragma unroll
            for (int np = 0; np < 4; np++) {
                const uint32_t off = (uint32_t)(((wn + np * 16 + l15) * PADH + kk + kofs) * 2);
                uint32_t bh[4], bl[4];
                LDSM4(bh, bh_b + off);
                LDSM4(bl, bl_b + off);
#pragma unroll
                for (int mt = 0; mt < 2; mt++) {
                    MMA16816(acc[mt][2 * np],     ah[mt], bh[0], bh[2]);
                    MMA16816(acc[mt][2 * np + 1], ah[mt], bh[1], bh[3]);
                    MMA16816(acc[mt][2 * np],     ah[mt], bl[0], bl[2]);
                    MMA16816(acc[mt][2 * np + 1], ah[mt], bl[1], bl[3]);
                }
            }
        }
        __syncthreads();
    }

    // epilogue: q and k both stored fp16
    const int r0 = m0 + wm + (lane >> 2);
    const int cbase = wn + ((lane & 3) << 1);
    __half* dstb = is_k ? g_kh : g_qh;
    const int coff = is_k ? CC : 0;
#pragma unroll
    for (int mt = 0; mt < 2; mt++) {
        const int row0 = r0 + mt * 16;
#pragma unroll
        for (int nt = 0; nt < 8; nt++) {
            const int col = n0 + cbase + nt * 8 - coff;
            float* a = acc[mt][nt];
            __half2 h0 = __floats2half2_rn(a[0], a[1]);
            __half2 h1 = __floats2half2_rn(a[2], a[3]);
            *(uint32_t*)(dstb + (size_t)row0 * CC + col)       = h2_bits(h0);
            *(uint32_t*)(dstb + (size_t)(row0 + 8) * CC + col) = h2_bits(h1);
        }
    }
}

// ---------------- Kernel 2: attention scores (paired neighbors) + flows_k ----
#define WBUF 1344   // per-warp smem floats (scores 1176 / flow expansion, reused)

__global__ __launch_bounds__(256)
void attn_kernel(const float* __restrict__ flows, float* __restrict__ out) {
    __shared__ float sbuf[8 * WBUF];
    __shared__ float mtab[8 * 48];   // per-warp mini tables: dt[3], diR[21], djR[21]

    const int tidx = threadIdx.x;
    const int wid = tidx >> 5;
    const int lane = tidx & 31;
    const int sl = lane & 15;       // sub-lane: 16 dims each
    const int hwh = lane >> 4;      // which neighbor of the pair

    const int t = blockIdx.z;
    const int h = blockIdx.y * 4 + (wid >> 1);
    const int w = blockIdx.x * 2 + (wid & 1);
    const int hw = h * WW + w;
    const int pix = t * (HH * WW) + hw;

    // q: 16 halves per lane (head = sl>>1), duplicated across half-warps
    const uint4* qp = (const uint4*)(g_qh + (size_t)pix * CC) + sl * 2;
    const uint4 qv0 = qp[0];
    const uint4 qv1 = qp[1];
    const __half2 q0 = *reinterpret_cast<const __half2*>(&qv0.x);
    const __half2 q1 = *reinterpret_cast<const __half2*>(&qv0.y);
    const __half2 q2 = *reinterpret_cast<const __half2*>(&qv0.z);
    const __half2 q3 = *reinterpret_cast<const __half2*>(&qv0.w);
    const __half2 q4 = *reinterpret_cast<const __half2*>(&qv1.x);
    const __half2 q5 = *reinterpret_cast<const __half2*>(&qv1.y);
    const __half2 q6 = *reinterpret_cast<const __half2*>(&qv1.z);
    const __half2 q7 = *reinterpret_cast<const __half2*>(&qv1.w);

    const int tp1 = (t + 1 < TT) ? t + 1 : t - 2;
    const int tp2 = (t - 1 >= 0) ? t - 1 : t + 2;

    const float f10 = flows[(4 * t + 0) * 4096 + hw];
    const float f11 = flows[(4 * t + 1) * 4096 + hw];
    const float f20 = flows[(4 * t + 2) * 4096 + hw];
    const float f21 = flows[(4 * t + 3) * 4096 + hw];

    const int di1 = __float2int_rn(f10), dj1 = __float2int_rn(f11);
    const int di2 = __float2int_rn(f20), dj2 = __float2int_rn(f21);

    const int tpr[3] = {t, tp1, tp2};
    const int dii[3] = {0, di1, di2};
    const int djj[3] = {0, dj1, dj2};

    float* srow = sbuf + wid * WBUF;
    float* mt = mtab + wid * 48;

    // ---- fill per-pixel mini tables (45 values; strided over 32 lanes) ----
    for (int idx = lane; idx < 45; idx += 32) {
        float v;
        if (idx < 3) {
            const int dtv = (idx == 0) ? 0 : (idx == 1 ? ((t + 1 < TT) ? 1 : -2)
                                                       : ((t - 1 >= 0) ? -1 : 2));
            v = (float)dtv;
        } else if (idx < 24) {
            const int l = idx - 3;
            const int s = l / 7, a = l - s * 7;
            const int ds = (s == 0) ? 0 : (s == 1 ? di1 : di2);
            v = (float)(reflect_idx(h + ds + a - 3) - h);
        } else {
            const int l = idx - 24;
            const int s = l / 7, b = l - s * 7;
            const int ds = (s == 0) ? 0 : (s == 1 ? dj1 : dj2);
            v = (float)(reflect_idx(w + ds + b - 3) - w);
        }
        mt[idx] = v;
    }

    // ---- scores: 2 neighbors per iteration (one per half-warp) ----
    const int head = sl >> 1;
    const bool do_store = ((lane & 1) == 0);
#pragma unroll
    for (int s = 0; s < 3; s++) {
        const __half* tslice = g_kh + (size_t)tpr[s] * (HH * WW) * CC;
        const int ci = h + dii[s];
        const int cj = w + djj[s];
        int ljo[4];
#pragma unroll
        for (int b2 = 0; b2 < 4; b2++)
            ljo[b2] = reflect_idx(cj + 2 * b2 + hwh - 3) * CC;

        for (int a = 0; a < WS; a++) {
            const int li = reflect_idx(ci + a - 3);
            const __half* row = tslice + (size_t)li * (WW * CC) + sl * 16;
#pragma unroll
            for (int b2 = 0; b2 < 4; b2++) {
                const uint4* kp = (const uint4*)(row + ljo[b2]);
                const uint4 k0 = kp[0];
                const uint4 k1 = kp[1];
                __half2 acc0 = __hmul2(q0, *reinterpret_cast<const __half2*>(&k0.x));
                acc0 = __hfma2(q1, *reinterpret_cast<const __half2*>(&k0.y), acc0);
                acc0 = __hfma2(q2, *reinterpret_cast<const __half2*>(&k0.z), acc0);
                acc0 = __hfma2(q3, *reinterpret_cast<const __half2*>(&k0.w), acc0);
                __half2 acc1 = __hmul2(q4, *reinterpret_cast<const __half2*>(&k1.x));
                acc1 = __hfma2(q5, *reinterpret_cast<const __half2*>(&k1.y), acc1);
                acc1 = __hfma2(q6, *reinterpret_cast<const __half2*>(&k1.z), acc1);
                acc1 = __hfma2(q7, *reinterpret_cast<const __half2*>(&k1.w), acc1);
                const float2 f0 = __half22float2(acc0);
                const float2 f1 = __half22float2(acc1);
                float p = (f0.x + f0.y) + (f1.x + f1.y);
                p += __shfl_xor_sync(0xffffffffu, p, 1);
                const int b = 2 * b2 + hwh;
                if (do_store && b < 7)
                    srow[head * NNB + s * 49 + a * 7 + b] = p;
            }
        }
    }
    __syncwarp();

    const float scale = 0.17677669529663687f;
#pragma unroll
    for (int hd = 0; hd < HEADS; hd++) {
        size_t obase = ((size_t)(hd * TT + t) * (HH * WW) + hw) * (size_t)NNB;
        for (int i = lane; i < NNB; i += 32)
            out[obase + i] = srow[hd * NNB + i] * scale;
    }
    __syncwarp();

    // ---- flows_k: expand mini tables into srow (reused), then replicate x8 ----
    const int basef = pix * (NNB * 3);       // float offset within a head slab
    const int pad = basef & 3;               // store element e at srow[pad+e]
    for (int n = lane; n < NNB; n += 32) {
        const int s = (n >= 98) ? 2 : ((n >= 49) ? 1 : 0);
        const int r = n - s * 49;
        const int a = r / 7;
        const int b = r - a * 7;
        const int o = pad + 3 * n;
        srow[o]     = mt[s];
        srow[o + 1] = mt[3 + s * 7 + a];
        srow[o + 2] = mt[24 + s * 7 + b];
    }
    __syncwarp();

    float* outF = out + (size_t)ATTN_ELEMS;
    const int lead = (4 - pad) & 3;
    const int nv4 = (NNB * 3 - lead) >> 2;
    const int tail = (NNB * 3 - lead) & 3;
    const float4* s4 = (const float4*)(srow + pad + lead);
#pragma unroll
    for (int hd = 0; hd < HEADS; hd++) {
        float* gp = outF + (size_t)hd * PER_HEAD_FLOW + basef;
        if (lane < lead) gp[lane] = srow[pad + lane];
        float4* g4 = (float4*)(gp + lead);
        for (int i = lane; i < nv4; i += 32) g4[i] = s4[i];
        if (lane < tail) gp[lead + 4 * nv4 + lane] = srow[pad + lead + 4 * nv4 + lane];
    }
}

// ---------------- launch ----------------
extern "C" void kernel_launch(void* const* d_in, const int* in_sizes, int n_in,
                              void* d_out, int out_size) {
    const float* x     = (const float*)d_in[0];
    const float* flows = (const float*)d_in[1];
    const float* Wm    = (const float*)d_in[2];
    float* out = (float*)d_out;

    cudaFuncSetAttribute(gemm_hmma, cudaFuncAttributeMaxDynamicSharedMemorySize, GSMEM);

    convert_split<<<1184, 256>>>(x, Wm);
    gemm_hmma<<<dim3(NW / BN, NPIX / BM), 256, GSMEM>>>();
    attn_kernel<<<dim3(WW / 2, HH / 4, TT), 256>>>(flows, out);
}

// round 16
// speedup vs baseline: 1.1784x; 1.1784x over previous
#include <cuda_runtime.h>
#include <cuda_fp16.h>
#include <cstdint>

// Problem constants
#define TT 8
#define HH 64
#define WW 64
#define CC 256
#define HEADS 8
#define WS 7
#define NNB 147
#define NPIX (TT*HH*WW)                 // 32768
#define ATTN_ELEMS (HEADS*TT*HH*WW*NNB) // 38,535,168
#define PER_HEAD_FLOW (TT*HH*WW*NNB*3)  // 14,450,688
#define NW 512                          // W rows (2*CC)

// Scratch
__device__ __half g_qh[(size_t)NPIX * CC];   // q fp16 [pix][256]
__device__ __half g_kh[(size_t)NPIX * CC];   // k fp16 [pix][256]
__device__ __half g_xh[(size_t)NPIX * CC];   // x hi
__device__ __half g_wh[(size_t)NW * CC];     // W hi
__device__ __half g_wl[(size_t)NW * CC];     // W lo

// ---------------- common helpers ----------------
__device__ __forceinline__ int reflect_idx(int idx) {
    int m = idx % 126;
    if (m < 0) m += 126;
    return (m > 63) ? (126 - m) : m;
}

__device__ __forceinline__ uint32_t h2_bits(__half2 v) {
    return *reinterpret_cast<uint32_t*>(&v);
}

__device__ __forceinline__ uint32_t smem_u32(const void* p) {
    uint32_t a;
    asm("{ .reg .u64 t; cvta.to.shared.u64 t, %1; cvt.u32.u64 %0, t; }" : "=r"(a) : "l"(p));
    return a;
}

__device__ __forceinline__ void cp16(uint32_t dst, const void* src) {
    asm volatile("cp.async.ca.shared.global [%0], [%1], 16;" :: "r"(dst), "l"(src));
}
#define CP_COMMIT() asm volatile("cp.async.commit_group;" ::: "memory")
#define CP_WAIT(n)  asm volatile("cp.async.wait_group %0;" :: "n"(n) : "memory")

#define LDSM4(r, a) \
    asm volatile("ldmatrix.sync.aligned.m8n8.x4.shared.b16 {%0,%1,%2,%3}, [%4];" \
                 : "=r"((r)[0]), "=r"((r)[1]), "=r"((r)[2]), "=r"((r)[3]) : "r"(a))

#define MMA16816(d, a, b0, b1) \
    asm volatile("mma.sync.aligned.m16n8k16.row.col.f32.f16.f16.f32 " \
                 "{%0,%1,%2,%3}, {%4,%5,%6,%7}, {%8,%9}, {%0,%1,%2,%3};" \
                 : "+f"((d)[0]), "+f"((d)[1]), "+f"((d)[2]), "+f"((d)[3]) \
                 : "r"((a)[0]), "r"((a)[1]), "r"((a)[2]), "r"((a)[3]), "r"(b0), "r"(b1))

// ---------------- Kernel 0: fp32 -> fp16 split ----------------
// x: hi only (2-term GEMM). W: hi + lo.
#define NV4X ((NPIX*CC)/4)   // 2,097,152
#define NV4W ((NW*CC)/4)     // 32,768

__global__ __launch_bounds__(256)
void convert_split(const float* __restrict__ x, const float* __restrict__ Wm) {
    const int total = NV4X + NV4W;
    for (int i = blockIdx.x * blockDim.x + threadIdx.x; i < total; i += gridDim.x * blockDim.x) {
        const float4 v = (i < NV4X) ? ((const float4*)x)[i] : ((const float4*)Wm)[i - NV4X];
        __half2 h01 = __floats2half2_rn(v.x, v.y);
        __half2 h23 = __floats2half2_rn(v.z, v.w);
        uint2 hv = make_uint2(h2_bits(h01), h2_bits(h23));
        if (i < NV4X) {
            ((uint2*)g_xh)[i] = hv;
        } else {
            float2 r01 = __half22float2(h01);
            float2 r23 = __half22float2(h23);
            __half2 l01 = __floats2half2_rn(v.x - r01.x, v.y - r01.y);
            __half2 l23 = __floats2half2_rn(v.z - r23.x, v.w - r23.y);
            ((uint2*)g_wh)[i - NV4X] = hv;
            ((uint2*)g_wl)[i - NV4X] = make_uint2(h2_bits(l01), h2_bits(l23));
        }
    }
}

// ---------------- Kernel 1: HMMA 2-term GEMM ----------------
// q|k[m][n] = sum_k x[m][k]*W[n][k] approx= xh*(wh+wl); fp32 accum HMMA
#define BM 128
#define BN 128
#define BK 32
#define NIT (CC/BK)                 // 8
#define PADH 40                     // halves per smem row (80B)
#define TILE_HALVES (128*PADH)
#define STAGE_HALVES (3*TILE_HALVES)
#define GSMEM (2*STAGE_HALVES*2)    // 61440 bytes

__device__ __forceinline__ void issue_stage(int it, int stage, int m0, int n0,
                                            uint32_t sbase, int tid) {
    const int kc = it * BK;
    const int r_lo = tid >> 2;
    const int c = (tid & 3) << 3;
#pragma unroll
    for (int q = 0; q < 6; q++) {
        const int tile = q >> 1;          // 0:xh 1:wh 2:wl
        const int r = ((q & 1) << 6) + r_lo;
        const __half* src;
        if (tile == 0)      src = g_xh + (size_t)(m0 + r) * CC + kc + c;
        else if (tile == 1) src = g_wh + (size_t)(n0 + r) * CC + kc + c;
        else                src = g_wl + (size_t)(n0 + r) * CC + kc + c;
        const uint32_t dst = sbase +
            (uint32_t)((stage * STAGE_HALVES + tile * TILE_HALVES + r * PADH + c) * 2);
        cp16(dst, src);
    }
}

__global__ __launch_bounds__(256)
void gemm_hmma(void) {
    extern __shared__ __half smem[];
    const uint32_t sbase = smem_u32(smem);
    const int tid = threadIdx.x;
    const int wid = tid >> 5;
    const int lane = tid & 31;

    const int n0 = blockIdx.x * BN;
    const int m0 = blockIdx.y * BM;
    const bool is_k = (n0 >= CC);

    const int wm = (wid >> 1) * 32;
    const int wn = (wid & 1) * 64;
    const int l15 = lane & 15;
    const int kofs = (lane >> 4) << 3;

    float acc[2][8][4];
#pragma unroll
    for (int i = 0; i < 2; i++)
#pragma unroll
        for (int j = 0; j < 8; j++)
#pragma unroll
            for (int c = 0; c < 4; c++) acc[i][j][c] = 0.0f;

    issue_stage(0, 0, m0, n0, sbase, tid);
    CP_COMMIT();

    for (int it = 0; it < NIT; it++) {
        if (it + 1 < NIT) {
            issue_stage(it + 1, (it + 1) & 1, m0, n0, sbase, tid);
            CP_COMMIT();
            CP_WAIT(1);
        } else {
            CP_WAIT(0);
        }
        __syncthreads();

        const uint32_t st = sbase + (uint32_t)(((it & 1) * STAGE_HALVES) * 2);
        const uint32_t ah_b = st;
        const uint32_t bh_b = st + TILE_HALVES * 2;
        const uint32_t bl_b = st + 2 * TILE_HALVES * 2;

#pragma unroll
        for (int kk = 0; kk < BK; kk += 16) {
            uint32_t ah[2][4];
#pragma unroll
            for (int mt = 0; mt < 2; mt++) {
                const uint32_t off = (uint32_t)(((wm + mt * 16 + l15) * PADH + kk + kofs) * 2);
                LDSM4(ah[mt], ah_b + off);
            }
#pragma unroll
            for (int np = 0; np < 4; np++) {
                const uint32_t off = (uint32_t)(((wn + np * 16 + l15) * PADH + kk + kofs) * 2);
                uint32_t bh[4], bl[4];
                LDSM4(bh, bh_b + off);
                LDSM4(bl, bl_b + off);
#pragma unroll
                for (int mt = 0; mt < 2; mt++) {
                    MMA16816(acc[mt][2 * np],     ah[mt], bh[0], bh[2]);
                    MMA16816(acc[mt][2 * np + 1], ah[mt], bh[1], bh[3]);
                    MMA16816(acc[mt][2 * np],     ah[mt], bl[0], bl[2]);
                    MMA16816(acc[mt][2 * np + 1], ah[mt], bl[1], bl[3]);
                }
            }
        }
        __syncthreads();
    }

    // epilogue: q and k both stored fp16
    const int r0 = m0 + wm + (lane >> 2);
    const int cbase = wn + ((lane & 3) << 1);
    __half* dstb = is_k ? g_kh : g_qh;
    const int coff = is_k ? CC : 0;
#pragma unroll
    for (int mt = 0; mt < 2; mt++) {
        const int row0 = r0 + mt * 16;
#pragma unroll
        for (int nt = 0; nt < 8; nt++) {
            const int col = n0 + cbase + nt * 8 - coff;
            float* a = acc[mt][nt];
            __half2 h0 = __floats2half2_rn(a[0], a[1]);
            __half2 h1 = __floats2half2_rn(a[2], a[3]);
            *(uint32_t*)(dstb + (size_t)row0 * CC + col)       = h2_bits(h0);
            *(uint32_t*)(dstb + (size_t)(row0 + 8) * CC + col) = h2_bits(h1);
        }
    }
}

// ---------------- Kernel 2: attention scores (half2, R12 layout) + flows_k ----
#define WBUF 1344   // per-warp smem floats (scores 1176 / flow expansion, reused)

__global__ __launch_bounds__(256)
void attn_kernel(const float* __restrict__ flows, float* __restrict__ out) {
    __shared__ float sbuf[8 * WBUF];
    __shared__ float mtab[8 * 48];   // per-warp mini tables: dt[3], diR[21], djR[21]

    const int tidx = threadIdx.x;
    const int wid = tidx >> 5;
    const int lane = tidx & 31;

    const int t = blockIdx.z;
    const int h = blockIdx.y * 4 + (wid >> 1);
    const int w = blockIdx.x * 2 + (wid & 1);
    const int hw = h * WW + w;
    const int pix = t * (HH * WW) + hw;

    // q fp16: 8 halves per lane (dims lane*8 .. +8), head = lane>>2
    const uint4 qv = *((const uint4*)(g_qh + (size_t)pix * CC) + lane);
    const __half2 q0 = *reinterpret_cast<const __half2*>(&qv.x);
    const __half2 q1 = *reinterpret_cast<const __half2*>(&qv.y);
    const __half2 q2 = *reinterpret_cast<const __half2*>(&qv.z);
    const __half2 q3 = *reinterpret_cast<const __half2*>(&qv.w);

    const int tp1 = (t + 1 < TT) ? t + 1 : t - 2;
    const int tp2 = (t - 1 >= 0) ? t - 1 : t + 2;

    const float f10 = flows[(4 * t + 0) * 4096 + hw];
    const float f11 = flows[(4 * t + 1) * 4096 + hw];
    const float f20 = flows[(4 * t + 2) * 4096 + hw];
    const float f21 = flows[(4 * t + 3) * 4096 + hw];

    const int di1 = __float2int_rn(f10), dj1 = __float2int_rn(f11);
    const int di2 = __float2int_rn(f20), dj2 = __float2int_rn(f21);

    const int tpr[3] = {t, tp1, tp2};
    const int dii[3] = {0, di1, di2};
    const int djj[3] = {0, dj1, dj2};

    float* srow = sbuf + wid * WBUF;
    float* mt = mtab + wid * 48;

    // ---- fill per-pixel mini tables (45 values; strided over 32 lanes) ----
    for (int idx = lane; idx < 45; idx += 32) {
        float v;
        if (idx < 3) {
            const int dtv = (idx == 0) ? 0 : (idx == 1 ? ((t + 1 < TT) ? 1 : -2)
                                                       : ((t - 1 >= 0) ? -1 : 2));
            v = (float)dtv;
        } else if (idx < 24) {
            const int l = idx - 3;
            const int s = l / 7, a = l - s * 7;
            const int ds = (s == 0) ? 0 : (s == 1 ? di1 : di2);
            v = (float)(reflect_idx(h + ds + a - 3) - h);
        } else {
            const int l = idx - 24;
            const int s = l / 7, b = l - s * 7;
            const int ds = (s == 0) ? 0 : (s == 1 ? dj1 : dj2);
            v = (float)(reflect_idx(w + ds + b - 3) - w);
        }
        mt[idx] = v;
    }

    // ---- scores (half2 inner product, fp32 cross-lane reduce) ----
#pragma unroll
    for (int s = 0; s < 3; s++) {
        const __half* tslice = g_kh + (size_t)tpr[s] * (HH * WW) * CC;
        const int ci = h + dii[s];
        const int cj = w + djj[s];
        int ljo[WS];
#pragma unroll
        for (int b = 0; b < WS; b++) ljo[b] = reflect_idx(cj + b - 3) * CC;

        for (int a = 0; a < WS; a++) {
            const int li = reflect_idx(ci + a - 3);
            const __half* rbase = tslice + (size_t)li * WW * CC;
#pragma unroll
            for (int b = 0; b < WS; b++) {
                const uint4 kv = *(const uint4*)(rbase + ljo[b] + lane * 8);
                const __half2 k0 = *reinterpret_cast<const __half2*>(&kv.x);
                const __half2 k1 = *reinterpret_cast<const __half2*>(&kv.y);
                const __half2 k2 = *reinterpret_cast<const __half2*>(&kv.z);
                const __half2 k3 = *reinterpret_cast<const __half2*>(&kv.w);
                __half2 acc = __hmul2(q0, k0);
                acc = __hfma2(q1, k1, acc);
                acc = __hfma2(q2, k2, acc);
                acc = __hfma2(q3, k3, acc);
                const float2 f = __half22float2(acc);
                float p = f.x + f.y;
                p += __shfl_xor_sync(0xffffffffu, p, 1);
                p += __shfl_xor_sync(0xffffffffu, p, 2);
                if ((lane & 3) == 0) {
                    srow[(lane >> 2) * NNB + s * 49 + a * 7 + b] = p;
                }
            }
        }
    }
    __syncwarp();

    const float scale = 0.17677669529663687f;
#pragma unroll
    for (int head = 0; head < HEADS; head++) {
        size_t obase = ((size_t)(head * TT + t) * (HH * WW) + hw) * (size_t)NNB;
        for (int i = lane; i < NNB; i += 32)
            out[obase + i] = srow[head * NNB + i] * scale;
    }
    __syncwarp();

    // ---- flows_k: expand mini tables into srow (reused), then replicate x8 ----
    const int basef = pix * (NNB * 3);       // float offset within a head slab
    const int pad = basef & 3;               // store element e at srow[pad+e]
    for (int n = lane; n < NNB; n += 32) {
        const int s = (n >= 98) ? 2 : ((n >= 49) ? 1 : 0);
        const int r = n - s * 49;
        const int a = r / 7;
        const int b = r - a * 7;
        const int o = pad + 3 * n;
        srow[o]     = mt[s];
        srow[o + 1] = mt[3 + s * 7 + a];
        srow[o + 2] = mt[24 + s * 7 + b];
    }
    __syncwarp();

    float* outF = out + (size_t)ATTN_ELEMS;
    const int lead = (4 - pad) & 3;
    const int nv4 = (NNB * 3 - lead) >> 2;
    const int tail = (NNB * 3 - lead) & 3;
    const float4* s4 = (const float4*)(srow + pad + lead);
#pragma unroll
    for (int head = 0; head < HEADS; head++) {
        float* gp = outF + (size_t)head * PER_HEAD_FLOW + basef;
        if (lane < lead) gp[lane] = srow[pad + lane];
        float4* g4 = (float4*)(gp + lead);
        for (int i = lane; i < nv4; i += 32) g4[i] = s4[i];
        if (lane < tail) gp[lead + 4 * nv4 + lane] = srow[pad + lead + 4 * nv4 + lane];
    }
}

// ---------------- launch ----------------
extern "C" void kernel_launch(void* const* d_in, const int* in_sizes, int n_in,
                              void* d_out, int out_size) {
    const float* x     = (const float*)d_in[0];
    const float* flows = (const float*)d_in[1];
    const float* Wm    = (const float*)d_in[2];
    float* out = (float*)d_out;

    cudaFuncSetAttribute(gemm_hmma, cudaFuncAttributeMaxDynamicSharedMemorySize, GSMEM);

    convert_split<<<1184, 256>>>(x, Wm);
    gemm_hmma<<<dim3(NW / BN, NPIX / BM), 256, GSMEM>>>();
    attn_kernel<<<dim3(WW / 2, HH / 4, TT), 256>>>(flows, out);
}